// round 13
// baseline (speedup 1.0000x reference)
#include <cuda_runtime.h>
#include <cuda_fp16.h>
#include <stdint.h>

#define NT    16384
#define DM    2048
#define NE    64
#define KC    64            // K per staged chunk
#define NCH   (DM / KC)     // 32 chunks
#define TPC   32            // tokens per CTA
#define WSTR  72            // W smem halves stride
#define ASTR  72            // A smem halves stride
#define LSTR  66            // partial-logits smem float stride (even)

#define WBUF  (2 * KC * WSTR * 2)     // 18432 (2 splits x 64k)
#define ABUF  (2 * TPC * ASTR * 2)    // 9216  (2 splits x 32tok)
#define A_OFF (2 * WBUF)              // 36864
#define SMEM_DYN (A_OFF + 2 * ABUF)   // 55296  -> 4 CTAs/SM fits 221KB

// W split (fp16), k-major [DM][NE]; w' = 4096w; w0 = h(w'), w1 = h((w'-w0)*4096)
__device__ __align__(16) __half g_w0[DM * NE];
__device__ __align__(16) __half g_w1[DM * NE];

__device__ __forceinline__ uint32_t smem_u32(const void* p) {
    uint32_t a;
    asm("{ .reg .u64 t; cvta.to.shared.u64 t, %1; cvt.u32.u64 %0, t; }" : "=r"(a) : "l"(p));
    return a;
}
__device__ __forceinline__ uint32_t h2u(__half2 h) {
    union { __half2 h; uint32_t u; } c; c.h = h; return c.u;
}
__device__ __forceinline__ void cpa16(uint32_t dst, const void* src) {
    asm volatile("cp.async.cg.shared.global [%0], [%1], 16;" :: "r"(dst), "l"(src));
}
__device__ __forceinline__ void ldmx4(uint32_t* r, uint32_t addr) {
    asm volatile("ldmatrix.sync.aligned.m8n8.x4.shared.b16 {%0,%1,%2,%3}, [%4];"
                 : "=r"(r[0]), "=r"(r[1]), "=r"(r[2]), "=r"(r[3]) : "r"(addr));
}
__device__ __forceinline__ void ldmx4t(uint32_t* r, uint32_t addr) {
    asm volatile("ldmatrix.sync.aligned.m8n8.x4.trans.shared.b16 {%0,%1,%2,%3}, [%4];"
                 : "=r"(r[0]), "=r"(r[1]), "=r"(r[2]), "=r"(r[3]) : "r"(addr));
}
__device__ __forceinline__ void mma16816(float* d,
        const uint32_t* a, uint32_t b0, uint32_t b1) {
    asm volatile("mma.sync.aligned.m16n8k16.row.col.f32.f16.f16.f32 "
                 "{%0,%1,%2,%3},{%4,%5,%6,%7},{%8,%9},{%0,%1,%2,%3};"
                 : "+f"(d[0]), "+f"(d[1]), "+f"(d[2]), "+f"(d[3])
                 : "r"(a[0]), "r"(a[1]), "r"(a[2]), "r"(a[3]), "r"(b0), "r"(b1));
}

// ---------------- prepass: split W ----------------
__global__ void wsplit(const float* __restrict__ W) {
    int i = blockIdx.x * 256 + threadIdx.x;
    float w = W[i] * 4096.0f;
    __half h0 = __float2half_rn(w);
    float r = (w - __half2float(h0)) * 4096.0f;
    g_w0[i] = h0;
    g_w1[i] = __float2half_rn(r);
}

// ---------------- main kernel ----------------
__global__ __launch_bounds__(128, 4)
void gating_mma(const float* __restrict__ x, const float* __restrict__ bias,
                float* __restrict__ out)
{
    extern __shared__ __align__(16) uint8_t smraw[];

    const int tid  = threadIdx.x;
    const int wid  = tid >> 5;
    const int lane = tid & 31;
    const int kh   = wid >> 1;          // K-half (0: ks 0-1, 1: ks 2-3)
    const int wn   = wid & 1;           // expert half (32)
    const int ct0  = blockIdx.x * TPC;

    const uint32_t smb = smem_u32(smraw);

    // ---- x map: f = j*128 + tid; row = f>>4 (32 rows), q = f&15 (coalesced float4) ----
    const int xrow0 = tid >> 4;         // rows 0..7 at j=0, stepping 8
    const int xq    = tid & 15;
    const float* xbase = x + (size_t)(ct0 + xrow0) * DM + (size_t)xq * 4;
    const uint32_t a_st0 = smb + A_OFF + (uint32_t)(xrow0 * ASTR + xq * 4) * 2;

    // ---- W staging: f = j*128 + tid; s = f>>9, krow = (f>>3)&63, q = f&7 ----
    auto stageW = [&](int c, int buf) {
        #pragma unroll
        for (int j = 0; j < 8; j++) {
            int f = j * 128 + tid;
            int s = f >> 9, krow = (f >> 3) & 63, q = f & 7;
            const uint4* gp = s ? (const uint4*)g_w1 : (const uint4*)g_w0;
            const uint4* src = gp + (size_t)(c * KC + krow) * 8 + q;
            uint32_t dst = smb + buf * WBUF
                + (uint32_t)((s * KC + krow) * WSTR + q * 8) * 2;
            cpa16(dst, src);
        }
        asm volatile("cp.async.commit_group;" ::: "memory");
    };

    float4 xf[4];
    auto loadX = [&](int c) {
        #pragma unroll
        for (int j = 0; j < 4; j++)
            xf[j] = *(const float4*)(xbase + (size_t)(j * 8) * DM + c * KC);
    };
    // x0 = h(x); x1 = h((x - x0)*4096)
    auto convA = [&](int bufidx) {
        const uint32_t ab = a_st0 + (uint32_t)bufidx * ABUF;
        #pragma unroll
        for (int j = 0; j < 4; j++) {
            float4 v = xf[j];
            __half2 h0a = __floats2half2_rn(v.x, v.y);
            __half2 h0b = __floats2half2_rn(v.z, v.w);
            float2 la = __half22float2(h0a), lb = __half22float2(h0b);
            __half2 h1a = __floats2half2_rn((v.x - la.x) * 4096.0f, (v.y - la.y) * 4096.0f);
            __half2 h1b = __floats2half2_rn((v.z - lb.x) * 4096.0f, (v.w - lb.y) * 4096.0f);
            uint32_t ad = ab + (uint32_t)(j * 8 * ASTR) * 2;
            asm volatile("st.shared.v2.b32 [%0], {%1,%2};"
                         :: "r"(ad), "r"(h2u(h0a)), "r"(h2u(h0b)) : "memory");
            asm volatile("st.shared.v2.b32 [%0], {%1,%2};"
                         :: "r"(ad + (uint32_t)(TPC * ASTR) * 2),
                            "r"(h2u(h1a)), "r"(h2u(h1b)) : "memory");
        }
    };

    // ---- per-warp ldmatrix bases ----
    // A (non-trans): row = mt*16 + (lane&15), col8 = (lane>>4)*8; single m32 tile
    const uint32_t aB0 = smb + A_OFF
        + (uint32_t)(((lane & 15)) * ASTR + (lane >> 4) * 8) * 2;
    // B (trans): krow = (lane&7)+((lane>>3)&1)*8; ncol = wn*32 + (lane>>4)*8
    const uint32_t bB0 = smb
        + (uint32_t)(((lane & 7) + ((lane >> 3) & 1) * 8) * WSTR
                     + wn * 32 + (lane >> 4) * 8) * 2;

    float acc1[2][4][4] = {}, acc2[2][4][4] = {};   // [mt][nt][frag]

    // ---- prologue ----
    stageW(0, 0);
    loadX(0);
    convA(0);
    loadX(1);

    for (int c = 0; c < NCH; ++c) {
        asm volatile("cp.async.wait_group 0;" ::: "memory");
        __syncthreads();   // W(c) + A(c) visible; A(c-1) readers retired

        if (c + 1 < NCH) stageW(c + 1, (c + 1) & 1);

        const uint32_t aB = aB0 + (uint32_t)(c & 1) * ABUF;
        const uint32_t bB = bB0 + (uint32_t)(c & 1) * WBUF;

        // this warp's K-half: ks = kh*2 + {0,1}
        #pragma unroll
        for (int ks2 = 0; ks2 < 2; ++ks2) {
            const int ks = kh * 2 + ks2;
            uint32_t a0[2][4], a1[2][4];       // [mt] split0/split1
            uint32_t b0[2][4], b1[2][4];       // [p16] split0/split1
            const uint32_t ao = (uint32_t)(ks * 16) * 2;
            ldmx4(a0[0], aB + ao);
            ldmx4(a0[1], aB + ao + (uint32_t)(16 * ASTR) * 2);
            ldmx4(a1[0], aB + ao + (uint32_t)(TPC * ASTR) * 2);
            ldmx4(a1[1], aB + ao + (uint32_t)((TPC + 16) * ASTR) * 2);
            const uint32_t ko = (uint32_t)(ks * 16 * WSTR) * 2;
            ldmx4t(b0[0], bB + ko);
            ldmx4t(b0[1], bB + ko + 32);
            ldmx4t(b1[0], bB + (uint32_t)(KC * WSTR) * 2 + ko);
            ldmx4t(b1[1], bB + (uint32_t)(KC * WSTR) * 2 + ko + 32);

            #pragma unroll
            for (int mt = 0; mt < 2; mt++) {
                mma16816(acc1[mt][0], a0[mt], b0[0][0], b0[0][1]);
                mma16816(acc1[mt][1], a0[mt], b0[0][2], b0[0][3]);
                mma16816(acc1[mt][2], a0[mt], b0[1][0], b0[1][1]);
                mma16816(acc1[mt][3], a0[mt], b0[1][2], b0[1][3]);
            }
            #pragma unroll
            for (int mt = 0; mt < 2; mt++) {
                mma16816(acc2[mt][0], a0[mt], b1[0][0], b1[0][1]);
                mma16816(acc2[mt][1], a0[mt], b1[0][2], b1[0][3]);
                mma16816(acc2[mt][2], a0[mt], b1[1][0], b1[1][1]);
                mma16816(acc2[mt][3], a0[mt], b1[1][2], b1[1][3]);
            }
            #pragma unroll
            for (int mt = 0; mt < 2; mt++) {
                mma16816(acc2[mt][0], a1[mt], b0[0][0], b0[0][1]);
                mma16816(acc2[mt][1], a1[mt], b0[0][2], b0[0][3]);
                mma16816(acc2[mt][2], a1[mt], b0[1][0], b0[1][1]);
                mma16816(acc2[mt][3], a1[mt], b0[1][2], b0[1][3]);
            }
        }

        // convert next chunk's A in the MMA shadow
        if (c + 1 < NCH) {
            convA((c + 1) & 1);
            if (c + 2 < NCH) loadX(c + 2);
        }
    }
    __syncthreads();   // all MMAs done before aliasing smem

    // ---- K-half partial logits: part[kh][token][expert] ----
    float* part = (float*)smraw;
    const float S2 = 1.0f / 4096.0f;
    const int gr = lane >> 2;
    const int gc = (lane & 3) * 2;
    #pragma unroll
    for (int mt = 0; mt < 2; mt++) {
        const int tl = mt * 16 + gr;
        #pragma unroll
        for (int nt = 0; nt < 4; nt++) {
            const int cc = wn * 32 + nt * 8 + gc;
            float p00 = acc1[mt][nt][0] + S2 * acc2[mt][nt][0];
            float p01 = acc1[mt][nt][1] + S2 * acc2[mt][nt][1];
            float p10 = acc1[mt][nt][2] + S2 * acc2[mt][nt][2];
            float p11 = acc1[mt][nt][3] + S2 * acc2[mt][nt][3];
            *(float2*)&part[(kh * TPC + tl)     * LSTR + cc] = make_float2(p00, p01);
            *(float2*)&part[(kh * TPC + tl + 8) * LSTR + cc] = make_float2(p10, p11);
        }
    }
    __syncthreads();

    // ---- per-token combine + softmax + top-2 (threads 0..31) ----
    if (tid < TPC) {
        const int t = ct0 + tid;
        float lg[NE];
        #pragma unroll
        for (int e = 0; e < NE; e++)
            lg[e] = (part[tid * LSTR + e] + part[(TPC + tid) * LSTR + e]) * S2
                    + __ldg(&bias[e]);

        float m = lg[0];
        #pragma unroll
        for (int e = 1; e < NE; e++) m = fmaxf(m, lg[e]);

        float l1 = lg[0], l2 = -3.4e38f; int i1 = 0, i2 = 0;
        #pragma unroll
        for (int e = 1; e < NE; e++) {
            float vv = lg[e];
            if (vv > l1)      { l2 = l1; i2 = i1; l1 = vv; i1 = e; }
            else if (vv > l2) { l2 = vv; i2 = e; }
        }

        float s = 0.0f;
        #pragma unroll
        for (int e = 0; e < NE; e++) { float w = __expf(lg[e] - m); lg[e] = w; s += w; }
        float inv = 1.0f / s;

        float* out_w = out + (size_t)NT * 4 + (size_t)t * NE;
        #pragma unroll
        for (int e4 = 0; e4 < NE / 4; e4++) {
            float4 o4 = make_float4(lg[e4*4] * inv, lg[e4*4+1] * inv,
                                    lg[e4*4+2] * inv, lg[e4*4+3] * inv);
            *(float4*)(out_w + e4 * 4) = o4;
        }
        float w1 = __expf(l1 - m) * inv;
        float w2 = __expf(l2 - m) * inv;
        *(float2*)(out + (size_t)t * 2)                  = make_float2(w1, w2);
        *(float2*)(out + (size_t)NT * 2 + (size_t)t * 2) = make_float2((float)i1, (float)i2);
    }
}

extern "C" void kernel_launch(void* const* d_in, const int* in_sizes, int n_in,
                              void* d_out, int out_size)
{
    const float* x = (const float*)d_in[0];
    const float* W = (const float*)d_in[1];
    const float* b = (const float*)d_in[2];
    float* out = (float*)d_out;

    wsplit<<<(DM * NE) / 256, 256>>>(W);

    cudaFuncSetAttribute(gating_mma, cudaFuncAttributeMaxDynamicSharedMemorySize, SMEM_DYN);
    gating_mma<<<NT / TPC, 128, SMEM_DYN>>>(x, b, out);
}

// round 14
// speedup vs baseline: 1.1153x; 1.1153x over previous
#include <cuda_runtime.h>
#include <cuda_fp16.h>
#include <stdint.h>

#define NT    16384
#define DM    2048
#define NE    64
#define KC    64            // K per chunk
#define NCH   (DM / KC)     // 32 chunks
#define TPC   64
#define WSTR  72            // W smem halves stride
#define ASTR  72            // A smem halves stride
#define LSTR  66            // logits smem float stride (even)

#define WBUF  (2 * KC * WSTR * 2)     // 18432
#define ABUF  (2 * TPC * ASTR * 2)    // 18432
#define A_OFF (2 * WBUF)              // 36864
#define SMEM_DYN (A_OFF + 2 * ABUF)   // 73728

// W split (fp16), k-major [DM][NE]; w' = 4096w; w0 = h(w'), w1 = h((w'-w0)*4096)
__device__ __align__(16) __half g_w0[DM * NE];
__device__ __align__(16) __half g_w1[DM * NE];

__device__ __forceinline__ uint32_t smem_u32(const void* p) {
    uint32_t a;
    asm("{ .reg .u64 t; cvta.to.shared.u64 t, %1; cvt.u32.u64 %0, t; }" : "=r"(a) : "l"(p));
    return a;
}
__device__ __forceinline__ uint32_t h2u(__half2 h) {
    union { __half2 h; uint32_t u; } c; c.h = h; return c.u;
}
__device__ __forceinline__ void cpa16(uint32_t dst, const void* src) {
    asm volatile("cp.async.cg.shared.global [%0], [%1], 16;" :: "r"(dst), "l"(src));
}
__device__ __forceinline__ void ldmx4(uint32_t* r, uint32_t addr) {
    asm volatile("ldmatrix.sync.aligned.m8n8.x4.shared.b16 {%0,%1,%2,%3}, [%4];"
                 : "=r"(r[0]), "=r"(r[1]), "=r"(r[2]), "=r"(r[3]) : "r"(addr));
}
__device__ __forceinline__ void ldmx4t(uint32_t* r, uint32_t addr) {
    asm volatile("ldmatrix.sync.aligned.m8n8.x4.trans.shared.b16 {%0,%1,%2,%3}, [%4];"
                 : "=r"(r[0]), "=r"(r[1]), "=r"(r[2]), "=r"(r[3]) : "r"(addr));
}
__device__ __forceinline__ void mma16816(float* d,
        const uint32_t* a, uint32_t b0, uint32_t b1) {
    asm volatile("mma.sync.aligned.m16n8k16.row.col.f32.f16.f16.f32 "
                 "{%0,%1,%2,%3},{%4,%5,%6,%7},{%8,%9},{%0,%1,%2,%3};"
                 : "+f"(d[0]), "+f"(d[1]), "+f"(d[2]), "+f"(d[3])
                 : "r"(a[0]), "r"(a[1]), "r"(a[2]), "r"(a[3]), "r"(b0), "r"(b1));
}

// ---------------- prepass: split W ----------------
__global__ void wsplit(const float* __restrict__ W) {
    int i = blockIdx.x * 256 + threadIdx.x;
    float w = W[i] * 4096.0f;
    __half h0 = __float2half_rn(w);
    float r = (w - __half2float(h0)) * 4096.0f;
    g_w0[i] = h0;
    g_w1[i] = __float2half_rn(r);
}

// ---------------- main kernel ----------------
__global__ __launch_bounds__(128, 2)
void gating_mma(const float* __restrict__ x, const float* __restrict__ bias,
                float* __restrict__ out)
{
    extern __shared__ __align__(16) uint8_t smraw[];
    __shared__ float s_bias[NE];

    const int tid  = threadIdx.x;
    const int wid  = tid >> 5;
    const int lane = tid & 31;
    const int wm   = wid >> 1;          // token 32-tile
    const int wn   = wid & 1;           // expert half (32)
    const int ct0  = blockIdx.x * TPC;

    if (tid < NE) s_bias[tid] = bias[tid];

    const uint32_t smb = smem_u32(smraw);

    // ---- x map: row = j*8 + (tid>>4), q = tid&15 (coalesced float4) ----
    const int xrow0 = tid >> 4;
    const int xq    = tid & 15;
    const float* xbase = x + (size_t)(ct0 + xrow0) * DM + (size_t)xq * 4;
    const uint32_t a_st0 = smb + A_OFF + (uint32_t)(xrow0 * ASTR + xq * 4) * 2;

    // ---- W staging: f = j*128 + tid; s = f>>9, krow = (f>>3)&63, q = f&7 ----
    auto stageW = [&](int c, int buf) {
        #pragma unroll
        for (int j = 0; j < 8; j++) {
            int f = j * 128 + tid;
            int s = f >> 9, krow = (f >> 3) & 63, q = f & 7;
            const uint4* gp = s ? (const uint4*)g_w1 : (const uint4*)g_w0;
            const uint4* src = gp + (size_t)(c * KC + krow) * 8 + q;
            uint32_t dst = smb + buf * WBUF
                + (uint32_t)((s * KC + krow) * WSTR + q * 8) * 2;
            cpa16(dst, src);
        }
        asm volatile("cp.async.commit_group;" ::: "memory");
    };

    float4 xf[8];
    auto loadX = [&](int c) {
        #pragma unroll
        for (int j = 0; j < 8; j++)
            xf[j] = *(const float4*)(xbase + (size_t)(j * 8) * DM + c * KC);
    };
    // x0 = h(x); x1 = h((x - x0)*4096)
    auto convA = [&](int bufidx) {
        const uint32_t ab = a_st0 + (uint32_t)bufidx * ABUF;
        #pragma unroll
        for (int j = 0; j < 8; j++) {
            float4 v = xf[j];
            __half2 h0a = __floats2half2_rn(v.x, v.y);
            __half2 h0b = __floats2half2_rn(v.z, v.w);
            float2 la = __half22float2(h0a), lb = __half22float2(h0b);
            __half2 h1a = __floats2half2_rn((v.x - la.x) * 4096.0f, (v.y - la.y) * 4096.0f);
            __half2 h1b = __floats2half2_rn((v.z - lb.x) * 4096.0f, (v.w - lb.y) * 4096.0f);
            uint32_t ad = ab + (uint32_t)(j * 8 * ASTR) * 2;
            asm volatile("st.shared.v2.b32 [%0], {%1,%2};"
                         :: "r"(ad), "r"(h2u(h0a)), "r"(h2u(h0b)) : "memory");
            asm volatile("st.shared.v2.b32 [%0], {%1,%2};"
                         :: "r"(ad + (uint32_t)(TPC * ASTR) * 2),
                            "r"(h2u(h1a)), "r"(h2u(h1b)) : "memory");
        }
    };

    // ---- per-warp ldmatrix bases ----
    const uint32_t aB0 = smb + A_OFF
        + (uint32_t)((wm * 32 + (lane & 15)) * ASTR + (lane >> 4) * 8) * 2;
    const uint32_t bB0 = smb
        + (uint32_t)(((lane & 7) + ((lane >> 3) & 1) * 8) * WSTR
                     + wn * 32 + (lane >> 4) * 8) * 2;

    float acc1[2][4][4] = {}, acc2[2][4][4] = {};

    // double-buffered fragments: [pb][mt or p][4]
    uint32_t fa0[2][2][4], fa1[2][2][4], fb0[2][2][4], fb1[2][2][4];

    // ---- prologue ----
    stageW(0, 0);
    loadX(0);
    convA(0);
    loadX(1);

    for (int c = 0; c < NCH; ++c) {
        asm volatile("cp.async.wait_group 0;" ::: "memory");
        __syncthreads();   // W(c) + A(c) visible; A(c-1) readers retired

        if (c + 1 < NCH) stageW(c + 1, (c + 1) & 1);

        const uint32_t aB = aB0 + (uint32_t)(c & 1) * ABUF;
        const uint32_t bB = bB0 + (uint32_t)(c & 1) * WBUF;

        // ---- load frags for ks=0 into buffer 0 ----
        {
            const uint32_t ao = 0, ko = 0;
            ldmx4 (fa0[0][0], aB + ao);
            ldmx4 (fa0[0][1], aB + ao + (uint32_t)(16 * ASTR) * 2);
            ldmx4 (fa1[0][0], aB + ao + (uint32_t)(TPC * ASTR) * 2);
            ldmx4 (fa1[0][1], aB + ao + (uint32_t)((TPC + 16) * ASTR) * 2);
            ldmx4t(fb0[0][0], bB + ko);
            ldmx4t(fb0[0][1], bB + ko + 32);
            ldmx4t(fb1[0][0], bB + (uint32_t)(KC * WSTR) * 2 + ko);
            ldmx4t(fb1[0][1], bB + (uint32_t)(KC * WSTR) * 2 + ko + 32);
        }

        #pragma unroll
        for (int ks = 0; ks < KC / 16; ++ks) {
            const int pb = ks & 1;
            // prefetch frags for ks+1 into the other buffer (hides LDS latency)
            if (ks + 1 < KC / 16) {
                const int nb = pb ^ 1;
                const uint32_t ao = (uint32_t)((ks + 1) * 16) * 2;
                const uint32_t ko = (uint32_t)((ks + 1) * 16 * WSTR) * 2;
                ldmx4 (fa0[nb][0], aB + ao);
                ldmx4 (fa0[nb][1], aB + ao + (uint32_t)(16 * ASTR) * 2);
                ldmx4 (fa1[nb][0], aB + ao + (uint32_t)(TPC * ASTR) * 2);
                ldmx4 (fa1[nb][1], aB + ao + (uint32_t)((TPC + 16) * ASTR) * 2);
                ldmx4t(fb0[nb][0], bB + ko);
                ldmx4t(fb0[nb][1], bB + ko + 32);
                ldmx4t(fb1[nb][0], bB + (uint32_t)(KC * WSTR) * 2 + ko);
                ldmx4t(fb1[nb][1], bB + (uint32_t)(KC * WSTR) * 2 + ko + 32);
            }

            // x0*w0 -> acc1, x0*w1 -> acc2, x1*w0 -> acc2
            #pragma unroll
            for (int mt = 0; mt < 2; mt++) {
                mma16816(acc1[mt][0], fa0[pb][mt], fb0[pb][0][0], fb0[pb][0][1]);
                mma16816(acc1[mt][1], fa0[pb][mt], fb0[pb][0][2], fb0[pb][0][3]);
                mma16816(acc1[mt][2], fa0[pb][mt], fb0[pb][1][0], fb0[pb][1][1]);
                mma16816(acc1[mt][3], fa0[pb][mt], fb0[pb][1][2], fb0[pb][1][3]);
            }
            #pragma unroll
            for (int mt = 0; mt < 2; mt++) {
                mma16816(acc2[mt][0], fa0[pb][mt], fb1[pb][0][0], fb1[pb][0][1]);
                mma16816(acc2[mt][1], fa0[pb][mt], fb1[pb][0][2], fb1[pb][0][3]);
                mma16816(acc2[mt][2], fa0[pb][mt], fb1[pb][1][0], fb1[pb][1][1]);
                mma16816(acc2[mt][3], fa0[pb][mt], fb1[pb][1][2], fb1[pb][1][3]);
            }
            #pragma unroll
            for (int mt = 0; mt < 2; mt++) {
                mma16816(acc2[mt][0], fa1[pb][mt], fb0[pb][0][0], fb0[pb][0][1]);
                mma16816(acc2[mt][1], fa1[pb][mt], fb0[pb][0][2], fb0[pb][0][3]);
                mma16816(acc2[mt][2], fa1[pb][mt], fb0[pb][1][0], fb0[pb][1][1]);
                mma16816(acc2[mt][3], fa1[pb][mt], fb0[pb][1][2], fb0[pb][1][3]);
            }
        }

        // convert next chunk's A in the MMA shadow
        if (c + 1 < NCH) {
            convA((c + 1) & 1);
            if (c + 2 < NCH) loadX(c + 2);
        }
    }
    __syncthreads();

    // ---- logits to SMEM (alias W region) ----
    float* slog = (float*)smraw;
    const float S2 = 1.0f / 4096.0f;
    const int gr = lane >> 2;
    const int gc = (lane & 3) * 2;
    #pragma unroll
    for (int mt = 0; mt < 2; mt++) {
        const int tl = wm * 32 + mt * 16 + gr;
        #pragma unroll
        for (int nt = 0; nt < 4; nt++) {
            const int cc = wn * 32 + nt * 8 + gc;
            float p00 = acc1[mt][nt][0] + S2 * acc2[mt][nt][0];
            float p01 = acc1[mt][nt][1] + S2 * acc2[mt][nt][1];
            float p10 = acc1[mt][nt][2] + S2 * acc2[mt][nt][2];
            float p11 = acc1[mt][nt][3] + S2 * acc2[mt][nt][3];
            *(float2*)&slog[tl * LSTR + cc]       = make_float2(p00, p01);
            *(float2*)&slog[(tl + 8) * LSTR + cc] = make_float2(p10, p11);
        }
    }
    __syncthreads();

    // ---- per-token softmax + top-2 (threads 0..63) ----
    if (tid < TPC) {
        const int t = ct0 + tid;
        float lg[NE];
        #pragma unroll
        for (int e = 0; e < NE; e++)
            lg[e] = slog[tid * LSTR + e] * S2 + s_bias[e];

        float m = lg[0];
        #pragma unroll
        for (int e = 1; e < NE; e++) m = fmaxf(m, lg[e]);

        float l1 = lg[0], l2 = -3.4e38f; int i1 = 0, i2 = 0;
        #pragma unroll
        for (int e = 1; e < NE; e++) {
            float vv = lg[e];
            if (vv > l1)      { l2 = l1; i2 = i1; l1 = vv; i1 = e; }
            else if (vv > l2) { l2 = vv; i2 = e; }
        }

        float s = 0.0f;
        #pragma unroll
        for (int e = 0; e < NE; e++) { float w = __expf(lg[e] - m); lg[e] = w; s += w; }
        float inv = 1.0f / s;

        float* out_w = out + (size_t)NT * 4 + (size_t)t * NE;
        #pragma unroll
        for (int e4 = 0; e4 < NE / 4; e4++) {
            float4 o4 = make_float4(lg[e4*4] * inv, lg[e4*4+1] * inv,
                                    lg[e4*4+2] * inv, lg[e4*4+3] * inv);
            *(float4*)(out_w + e4 * 4) = o4;
        }
        float w1 = __expf(l1 - m) * inv;
        float w2 = __expf(l2 - m) * inv;
        *(float2*)(out + (size_t)t * 2)                  = make_float2(w1, w2);
        *(float2*)(out + (size_t)NT * 2 + (size_t)t * 2) = make_float2((float)i1, (float)i2);
    }
}

extern "C" void kernel_launch(void* const* d_in, const int* in_sizes, int n_in,
                              void* d_out, int out_size)
{
    const float* x = (const float*)d_in[0];
    const float* W = (const float*)d_in[1];
    const float* b = (const float*)d_in[2];
    float* out = (float*)d_out;

    wsplit<<<(DM * NE) / 256, 256>>>(W);

    cudaFuncSetAttribute(gating_mma, cudaFuncAttributeMaxDynamicSharedMemorySize, SMEM_DYN);
    gating_mma<<<NT / TPC, 128, SMEM_DYN>>>(x, b, out);
}

// round 15
// speedup vs baseline: 1.1683x; 1.0475x over previous
#include <cuda_runtime.h>
#include <cuda_fp16.h>
#include <stdint.h>

#define NT    16384
#define DM    2048
#define NE    64
#define KC    64            // K per chunk
#define NCH   (DM / KC)     // 32 chunks
#define TPC   64
#define WSTR  72            // W smem halves stride
#define ASTR  72            // A smem halves stride
#define LSTR  66            // logits smem float stride (even)

#define WBUF  (2 * KC * WSTR * 2)     // 18432
#define ABUF  (2 * TPC * ASTR * 2)    // 18432
#define A_OFF (2 * WBUF)              // 36864
#define SMEM_DYN (A_OFF + 2 * ABUF)   // 73728

#define NTHREADS 192        // 4 consumer warps + 2 producer warps
#define BAR_FULL(b)  (1 + (b))
#define BAR_EMPTY(b) (3 + (b))

// W split (fp16), k-major [DM][NE]; w' = 4096w; w0 = h(w'), w1 = h((w'-w0)*4096)
__device__ __align__(16) __half g_w0[DM * NE];
__device__ __align__(16) __half g_w1[DM * NE];

__device__ __forceinline__ uint32_t smem_u32(const void* p) {
    uint32_t a;
    asm("{ .reg .u64 t; cvta.to.shared.u64 t, %1; cvt.u32.u64 %0, t; }" : "=r"(a) : "l"(p));
    return a;
}
__device__ __forceinline__ uint32_t h2u(__half2 h) {
    union { __half2 h; uint32_t u; } c; c.h = h; return c.u;
}
__device__ __forceinline__ void cpa16(uint32_t dst, const void* src) {
    asm volatile("cp.async.cg.shared.global [%0], [%1], 16;" :: "r"(dst), "l"(src));
}
__device__ __forceinline__ void bar_sync(int id) {
    asm volatile("bar.sync %0, %1;" :: "r"(id), "n"(NTHREADS) : "memory");
}
__device__ __forceinline__ void bar_arrive(int id) {
    asm volatile("bar.arrive %0, %1;" :: "r"(id), "n"(NTHREADS) : "memory");
}
__device__ __forceinline__ void ldmx4(uint32_t* r, uint32_t addr) {
    asm volatile("ldmatrix.sync.aligned.m8n8.x4.shared.b16 {%0,%1,%2,%3}, [%4];"
                 : "=r"(r[0]), "=r"(r[1]), "=r"(r[2]), "=r"(r[3]) : "r"(addr));
}
__device__ __forceinline__ void ldmx4t(uint32_t* r, uint32_t addr) {
    asm volatile("ldmatrix.sync.aligned.m8n8.x4.trans.shared.b16 {%0,%1,%2,%3}, [%4];"
                 : "=r"(r[0]), "=r"(r[1]), "=r"(r[2]), "=r"(r[3]) : "r"(addr));
}
__device__ __forceinline__ void mma16816(float* d,
        const uint32_t* a, uint32_t b0, uint32_t b1) {
    asm volatile("mma.sync.aligned.m16n8k16.row.col.f32.f16.f16.f32 "
                 "{%0,%1,%2,%3},{%4,%5,%6,%7},{%8,%9},{%0,%1,%2,%3};"
                 : "+f"(d[0]), "+f"(d[1]), "+f"(d[2]), "+f"(d[3])
                 : "r"(a[0]), "r"(a[1]), "r"(a[2]), "r"(a[3]), "r"(b0), "r"(b1));
}

// ---------------- prepass: split W ----------------
__global__ void wsplit(const float* __restrict__ W) {
    int i = blockIdx.x * 256 + threadIdx.x;
    float w = W[i] * 4096.0f;
    __half h0 = __float2half_rn(w);
    float r = (w - __half2float(h0)) * 4096.0f;
    g_w0[i] = h0;
    g_w1[i] = __float2half_rn(r);
}

// ---------------- main kernel ----------------
__global__ __launch_bounds__(NTHREADS, 2)
void gating_mma(const float* __restrict__ x, const float* __restrict__ bias,
                float* __restrict__ out)
{
    extern __shared__ __align__(16) uint8_t smraw[];
    __shared__ float s_bias[NE];

    const int tid  = threadIdx.x;
    const int wid  = tid >> 5;
    const int lane = tid & 31;
    const int ct0  = blockIdx.x * TPC;

    if (tid < NE) s_bias[tid] = bias[tid];

    const uint32_t smb = smem_u32(smraw);

    if (wid >= 4) {
        // ================= PRODUCER (warps 4-5, 64 threads) =================
        const int ptid = tid & 63;
        const int prow = ptid >> 4;      // 0..3
        const int pq   = ptid & 15;      // float4 col within 64-k chunk
        const float* xsrc = x + (size_t)(ct0 + prow) * DM + (size_t)pq * 4;
        const uint32_t a_st0 = smb + A_OFF + (uint32_t)(prow * ASTR + pq * 4) * 2;

        // W map per i: split = i>>3, krow = (i&7)*8 + (ptid>>3), q8 = ptid&7
        const int pk = ptid >> 3;
        const int q8 = ptid & 7;

        float4 xv[16];
        // prologue: x(0)
        #pragma unroll
        for (int i = 0; i < 16; i++)
            xv[i] = *(const float4*)(xsrc + (size_t)(i * 4) * DM);

        for (int c = 0; c < NCH; ++c) {
            const int b = c & 1;
            if (c >= 2) bar_sync(BAR_EMPTY(b));   // consumers done with buf b

            // stage W(c) via cp.async
            #pragma unroll
            for (int i = 0; i < 16; i++) {
                const int s = i >> 3;
                const int krow = (i & 7) * 8 + pk;
                const uint4* gp = s ? (const uint4*)g_w1 : (const uint4*)g_w0;
                cpa16(smb + b * WBUF + (uint32_t)((s * KC + krow) * WSTR + q8 * 8) * 2,
                      gp + (size_t)(c * KC + krow) * 8 + q8);
            }
            asm volatile("cp.async.commit_group;" ::: "memory");

            // convert + STS A(c) from xv
            const uint32_t ab = a_st0 + (uint32_t)b * ABUF;
            #pragma unroll
            for (int i = 0; i < 16; i++) {
                float4 v = xv[i];
                __half2 h0a = __floats2half2_rn(v.x, v.y);
                __half2 h0b = __floats2half2_rn(v.z, v.w);
                float2 la = __half22float2(h0a), lb = __half22float2(h0b);
                __half2 h1a = __floats2half2_rn((v.x - la.x) * 4096.0f, (v.y - la.y) * 4096.0f);
                __half2 h1b = __floats2half2_rn((v.z - lb.x) * 4096.0f, (v.w - lb.y) * 4096.0f);
                uint32_t ad = ab + (uint32_t)(i * 4 * ASTR) * 2;
                asm volatile("st.shared.v2.b32 [%0], {%1,%2};"
                             :: "r"(ad), "r"(h2u(h0a)), "r"(h2u(h0b)) : "memory");
                asm volatile("st.shared.v2.b32 [%0], {%1,%2};"
                             :: "r"(ad + (uint32_t)(TPC * ASTR) * 2),
                                "r"(h2u(h1a)), "r"(h2u(h1b)) : "memory");
            }

            // prefetch x(c+1)
            if (c + 1 < NCH) {
                #pragma unroll
                for (int i = 0; i < 16; i++)
                    xv[i] = *(const float4*)(xsrc + (size_t)(i * 4) * DM + (c + 1) * KC);
            }

            asm volatile("cp.async.wait_group 0;" ::: "memory");   // W(c) landed
            bar_arrive(BAR_FULL(b));
        }
    } else {
        // ================= CONSUMER (warps 0-3, pure MMA) =================
        const int wm = wid >> 1;          // token 32-tile
        const int wn = wid & 1;           // expert half

        const uint32_t aB0 = smb + A_OFF
            + (uint32_t)((wm * 32 + (lane & 15)) * ASTR + (lane >> 4) * 8) * 2;
        const uint32_t bB0 = smb
            + (uint32_t)(((lane & 7) + ((lane >> 3) & 1) * 8) * WSTR
                         + wn * 32 + (lane >> 4) * 8) * 2;

        float acc1[2][4][4] = {}, acc2[2][4][4] = {};
        uint32_t fa0[2][2][4], fa1[2][2][4], fb0[2][2][4], fb1[2][2][4];

        for (int c = 0; c < NCH; ++c) {
            const int b = c & 1;
            bar_sync(BAR_FULL(b));        // W(c)+A(c) ready in buf b

            const uint32_t aB = aB0 + (uint32_t)b * ABUF;
            const uint32_t bB = bB0 + (uint32_t)b * WBUF;

            // frags for ks=0
            ldmx4 (fa0[0][0], aB);
            ldmx4 (fa0[0][1], aB + (uint32_t)(16 * ASTR) * 2);
            ldmx4 (fa1[0][0], aB + (uint32_t)(TPC * ASTR) * 2);
            ldmx4 (fa1[0][1], aB + (uint32_t)((TPC + 16) * ASTR) * 2);
            ldmx4t(fb0[0][0], bB);
            ldmx4t(fb0[0][1], bB + 32);
            ldmx4t(fb1[0][0], bB + (uint32_t)(KC * WSTR) * 2);
            ldmx4t(fb1[0][1], bB + (uint32_t)(KC * WSTR) * 2 + 32);

            #pragma unroll
            for (int ks = 0; ks < KC / 16; ++ks) {
                const int pb = ks & 1;
                if (ks + 1 < KC / 16) {
                    const int nb = pb ^ 1;
                    const uint32_t ao = (uint32_t)((ks + 1) * 16) * 2;
                    const uint32_t ko = (uint32_t)((ks + 1) * 16 * WSTR) * 2;
                    ldmx4 (fa0[nb][0], aB + ao);
                    ldmx4 (fa0[nb][1], aB + ao + (uint32_t)(16 * ASTR) * 2);
                    ldmx4 (fa1[nb][0], aB + ao + (uint32_t)(TPC * ASTR) * 2);
                    ldmx4 (fa1[nb][1], aB + ao + (uint32_t)((TPC + 16) * ASTR) * 2);
                    ldmx4t(fb0[nb][0], bB + ko);
                    ldmx4t(fb0[nb][1], bB + ko + 32);
                    ldmx4t(fb1[nb][0], bB + (uint32_t)(KC * WSTR) * 2 + ko);
                    ldmx4t(fb1[nb][1], bB + (uint32_t)(KC * WSTR) * 2 + ko + 32);
                }
                #pragma unroll
                for (int mt = 0; mt < 2; mt++) {
                    mma16816(acc1[mt][0], fa0[pb][mt], fb0[pb][0][0], fb0[pb][0][1]);
                    mma16816(acc1[mt][1], fa0[pb][mt], fb0[pb][0][2], fb0[pb][0][3]);
                    mma16816(acc1[mt][2], fa0[pb][mt], fb0[pb][1][0], fb0[pb][1][1]);
                    mma16816(acc1[mt][3], fa0[pb][mt], fb0[pb][1][2], fb0[pb][1][3]);
                }
                #pragma unroll
                for (int mt = 0; mt < 2; mt++) {
                    mma16816(acc2[mt][0], fa0[pb][mt], fb1[pb][0][0], fb1[pb][0][1]);
                    mma16816(acc2[mt][1], fa0[pb][mt], fb1[pb][0][2], fb1[pb][0][3]);
                    mma16816(acc2[mt][2], fa0[pb][mt], fb1[pb][1][0], fb1[pb][1][1]);
                    mma16816(acc2[mt][3], fa0[pb][mt], fb1[pb][1][2], fb1[pb][1][3]);
                }
                #pragma unroll
                for (int mt = 0; mt < 2; mt++) {
                    mma16816(acc2[mt][0], fa1[pb][mt], fb0[pb][0][0], fb0[pb][0][1]);
                    mma16816(acc2[mt][1], fa1[pb][mt], fb0[pb][0][2], fb0[pb][0][3]);
                    mma16816(acc2[mt][2], fa1[pb][mt], fb0[pb][1][0], fb0[pb][1][1]);
                    mma16816(acc2[mt][3], fa1[pb][mt], fb0[pb][1][2], fb0[pb][1][3]);
                }
            }
            bar_arrive(BAR_EMPTY(b));
        }

        __syncthreads();   // (bar 0, all 192) — producers join below

        // ---- logits to SMEM (alias buffers) ----
        float* slog = (float*)smraw;
        const float S2 = 1.0f / 4096.0f;
        const int gr = lane >> 2;
        const int gc = (lane & 3) * 2;
        #pragma unroll
        for (int mt = 0; mt < 2; mt++) {
            const int tl = wm * 32 + mt * 16 + gr;
            #pragma unroll
            for (int nt = 0; nt < 4; nt++) {
                const int cc = wn * 32 + nt * 8 + gc;
                float p00 = acc1[mt][nt][0] + S2 * acc2[mt][nt][0];
                float p01 = acc1[mt][nt][1] + S2 * acc2[mt][nt][1];
                float p10 = acc1[mt][nt][2] + S2 * acc2[mt][nt][2];
                float p11 = acc1[mt][nt][3] + S2 * acc2[mt][nt][3];
                *(float2*)&slog[tl * LSTR + cc]       = make_float2(p00, p01);
                *(float2*)&slog[(tl + 8) * LSTR + cc] = make_float2(p10, p11);
            }
        }
    }

    if (wid >= 4) __syncthreads();   // producers' matching bar 0
    __syncthreads();                 // all: logits visible

    // ---- per-token softmax + top-2 (threads 0..63) ----
    if (tid < TPC) {
        float* slog = (float*)smraw;
        const float S2 = 1.0f / 4096.0f;
        const int t = ct0 + tid;
        float lg[NE];
        #pragma unroll
        for (int e = 0; e < NE; e++)
            lg[e] = slog[tid * LSTR + e] * S2 + s_bias[e];

        float m = lg[0];
        #pragma unroll
        for (int e = 1; e < NE; e++) m = fmaxf(m, lg[e]);

        float l1 = lg[0], l2 = -3.4e38f; int i1 = 0, i2 = 0;
        #pragma unroll
        for (int e = 1; e < NE; e++) {
            float vv = lg[e];
            if (vv > l1)      { l2 = l1; i2 = i1; l1 = vv; i1 = e; }
            else if (vv > l2) { l2 = vv; i2 = e; }
        }

        float s = 0.0f;
        #pragma unroll
        for (int e = 0; e < NE; e++) { float w = __expf(lg[e] - m); lg[e] = w; s += w; }
        float inv = 1.0f / s;

        float* out_w = out + (size_t)NT * 4 + (size_t)t * NE;
        #pragma unroll
        for (int e4 = 0; e4 < NE / 4; e4++) {
            float4 o4 = make_float4(lg[e4*4] * inv, lg[e4*4+1] * inv,
                                    lg[e4*4+2] * inv, lg[e4*4+3] * inv);
            *(float4*)(out_w + e4 * 4) = o4;
        }
        float w1 = __expf(l1 - m) * inv;
        float w2 = __expf(l2 - m) * inv;
        *(float2*)(out + (size_t)t * 2)                  = make_float2(w1, w2);
        *(float2*)(out + (size_t)NT * 2 + (size_t)t * 2) = make_float2((float)i1, (float)i2);
    }
}

extern "C" void kernel_launch(void* const* d_in, const int* in_sizes, int n_in,
                              void* d_out, int out_size)
{
    const float* x = (const float*)d_in[0];
    const float* W = (const float*)d_in[1];
    const float* b = (const float*)d_in[2];
    float* out = (float*)d_out;

    wsplit<<<(DM * NE) / 256, 256>>>(W);

    cudaFuncSetAttribute(gating_mma, cudaFuncAttributeMaxDynamicSharedMemorySize, SMEM_DYN);
    gating_mma<<<NT / TPC, NTHREADS, SMEM_DYN>>>(x, b, out);
}